// round 8
// baseline (speedup 1.0000x reference)
#include <cuda_runtime.h>
#include <cuda_bf16.h>

// ActivationQuantizer: per-token (row-wise over last dim) asymmetric fake quant.
// x: [4, 4096, 4096] fp32 -> out same shape.
//   xmin/xmax over last dim
//   scale = clamp((xmax - xmin)/255, 1e-5, 1e4)
//   zp    = clamp(-xmin/scale, -1e4, 1e4)       (NOT rounded)
//   xi    = clamp(rint(x/scale) + zp, 0, 255)
//   out   = (xi - zp) * scale
//
// Strategy: PERSISTENT CTAs (grid = SMs x occupancy), grid-stride loop over
// rows. Per row: 256 threads x 16 floats register-resident (4x float4),
// single pass: load -> blockwide min/max reduce -> quantize from registers
// -> store. Exactly 1R + 1W HBM traffic. Persistent grid removes the
// (n_waves-1)*T_wave_trans term of the B300 T_chip model (~22 waves at
// occ~5 for a 16384-CTA launch).
// __ldcs/__stcs streaming hints: no reuse, keep the stream out of L2.
// All divisions via __fdiv_rn to exactly match JAX fp32 semantics and stay
// immune to any --use_fast_math in the harness build.

#define ROW_LEN   4096
#define NTHREADS  256
#define VEC_PER_T 4          // 4 float4 = 16 floats per thread
#define QMAX_F    255.0f
#define CLIPMIN_F 1e-5f
#define CLIPMAX_F 10000.0f

__global__ __launch_bounds__(NTHREADS)
void act_quant_kernel(const float* __restrict__ x, float* __restrict__ out,
                      int n_rows)
{
    const int tid = threadIdx.x;
    const int wid = tid >> 5;
    const int lid = tid & 31;

    __shared__ float smn[NTHREADS / 32];
    __shared__ float smx[NTHREADS / 32];

    for (int row = blockIdx.x; row < n_rows; row += gridDim.x) {
        const float4* __restrict__ xrow =
            reinterpret_cast<const float4*>(x + (long long)row * ROW_LEN);
        float4* __restrict__ orow =
            reinterpret_cast<float4*>(out + (long long)row * ROW_LEN);

        // ---- load 16 floats into registers (coalesced float4, streaming) ----
        float4 v[VEC_PER_T];
#pragma unroll
        for (int i = 0; i < VEC_PER_T; ++i) {
            v[i] = __ldcs(&xrow[tid + i * NTHREADS]);
        }

        // ---- per-thread min/max ----
        float mn = v[0].x, mx = v[0].x;
#pragma unroll
        for (int i = 0; i < VEC_PER_T; ++i) {
            mn = fminf(mn, v[i].x); mx = fmaxf(mx, v[i].x);
            mn = fminf(mn, v[i].y); mx = fmaxf(mx, v[i].y);
            mn = fminf(mn, v[i].z); mx = fmaxf(mx, v[i].z);
            mn = fminf(mn, v[i].w); mx = fmaxf(mx, v[i].w);
        }

        // ---- warp reduce ----
#pragma unroll
        for (int off = 16; off > 0; off >>= 1) {
            mn = fminf(mn, __shfl_xor_sync(0xFFFFFFFFu, mn, off));
            mx = fmaxf(mx, __shfl_xor_sync(0xFFFFFFFFu, mx, off));
        }

        // ---- cross-warp reduce via smem ----
        if (lid == 0) { smn[wid] = mn; smx[wid] = mx; }
        __syncthreads();
        if (wid == 0) {
            float a = (lid < NTHREADS / 32) ? smn[lid] :  3.4e38f;
            float b = (lid < NTHREADS / 32) ? smx[lid] : -3.4e38f;
#pragma unroll
            for (int off = 4; off > 0; off >>= 1) {
                a = fminf(a, __shfl_xor_sync(0xFFFFFFFFu, a, off));
                b = fmaxf(b, __shfl_xor_sync(0xFFFFFFFFu, b, off));
            }
            if (lid == 0) { smn[0] = a; smx[0] = b; }
        }
        __syncthreads();
        const float xmin = smn[0];
        const float xmax = smx[0];

        // ---- scale / zero_point (exact IEEE-RN division, match reference) ----
        float scale = __fdiv_rn(xmax - xmin, QMAX_F);
        scale = fminf(fmaxf(scale, CLIPMIN_F), CLIPMAX_F);
        float zp = __fdiv_rn(-xmin, scale);
        zp = fminf(fmaxf(zp, -CLIPMAX_F), CLIPMAX_F);

        // ---- quantize from registers, store (streaming) ----
#pragma unroll
        for (int i = 0; i < VEC_PER_T; ++i) {
            float4 o;
            {
                float xi = rintf(__fdiv_rn(v[i].x, scale)) + zp;
                xi = fminf(fmaxf(xi, 0.0f), QMAX_F);
                o.x = (xi - zp) * scale;
            }
            {
                float xi = rintf(__fdiv_rn(v[i].y, scale)) + zp;
                xi = fminf(fmaxf(xi, 0.0f), QMAX_F);
                o.y = (xi - zp) * scale;
            }
            {
                float xi = rintf(__fdiv_rn(v[i].z, scale)) + zp;
                xi = fminf(fmaxf(xi, 0.0f), QMAX_F);
                o.z = (xi - zp) * scale;
            }
            {
                float xi = rintf(__fdiv_rn(v[i].w, scale)) + zp;
                xi = fminf(fmaxf(xi, 0.0f), QMAX_F);
                o.w = (xi - zp) * scale;
            }
            __stcs(&orow[tid + i * NTHREADS], o);
        }

        // Barrier before next iteration reuses smn/smx (warp 0 may race ahead
        // and overwrite smn[0] while slow warps still read it otherwise).
        __syncthreads();
    }
}

extern "C" void kernel_launch(void* const* d_in, const int* in_sizes, int n_in,
                              void* d_out, int out_size)
{
    const float* x = (const float*)d_in[0];
    float* out = (float*)d_out;
    const int n_rows = in_sizes[0] / ROW_LEN;   // 4*4096*4096 / 4096 = 16384

    // Occupancy-sized persistent grid. Host-side queries only (no allocation);
    // executed at graph-capture time, deterministic.
    int dev = 0;
    cudaGetDevice(&dev);
    int sms = 148;
    cudaDeviceGetAttribute(&sms, cudaDevAttrMultiProcessorCount, dev);
    int occ = 4;
    cudaOccupancyMaxActiveBlocksPerMultiprocessor(&occ, act_quant_kernel,
                                                  NTHREADS, 0);
    if (occ < 1) occ = 1;
    int grid = sms * occ;
    if (grid > n_rows) grid = n_rows;

    act_quant_kernel<<<grid, NTHREADS>>>(x, out, n_rows);
}

// round 10
// speedup vs baseline: 1.0391x; 1.0391x over previous
#include <cuda_runtime.h>
#include <cuda_bf16.h>

// ActivationQuantizer: per-token (row-wise over last dim) asymmetric fake quant.
// x: [4, 4096, 4096] fp32 -> out same shape.
//
// R8 changes vs R7 (measured: 82.5us kernel, DRAM 73.9%, fma 19.6%):
//  1. Software pipeline: prefetch next row's 16 floats BEFORE the current
//     row's reduce/quantize, so DRAM stays busy through the compute tail.
//  2. Reciprocal-multiply instead of per-element __fdiv_rn (16 divs -> 1 div
//     + 16 FMULs); shrinks the compute tail ~3x. Error <= ~1ulp pre-rint,
//     rel_err headroom is 27x.
//  3. Parity double-buffered smem reduce slots: trailing __syncthreads gone.

#define ROW_LEN   4096
#define NTHREADS  256
#define VEC_PER_T 4          // 4 float4 = 16 floats per thread
#define NWARPS    (NTHREADS / 32)
#define QMAX_F    255.0f
#define CLIPMIN_F 1e-5f
#define CLIPMAX_F 10000.0f

__global__ __launch_bounds__(NTHREADS)
void act_quant_kernel(const float* __restrict__ x, float* __restrict__ out,
                      int n_rows)
{
    const int tid = threadIdx.x;
    const int wid = tid >> 5;
    const int lid = tid & 31;

    // parity double-buffered reduce slots
    __shared__ float smn[2][NWARPS];
    __shared__ float smx[2][NWARPS];

    int row = blockIdx.x;
    if (row >= n_rows) return;

    // ---- preload first row ----
    float4 v[VEC_PER_T];
    {
        const float4* __restrict__ xrow =
            reinterpret_cast<const float4*>(x + (long long)row * ROW_LEN);
#pragma unroll
        for (int i = 0; i < VEC_PER_T; ++i)
            v[i] = __ldcs(&xrow[tid + i * NTHREADS]);
    }

    int parity = 0;
    for (; row < n_rows; row += gridDim.x, parity ^= 1) {
        const int next = row + gridDim.x;

        // ---- prefetch next row (loads in flight during reduce+quantize) ----
        float4 vn[VEC_PER_T];
        if (next < n_rows) {
            const float4* __restrict__ xnext =
                reinterpret_cast<const float4*>(x + (long long)next * ROW_LEN);
#pragma unroll
            for (int i = 0; i < VEC_PER_T; ++i)
                vn[i] = __ldcs(&xnext[tid + i * NTHREADS]);
        }

        // ---- per-thread min/max over current row ----
        float mn = v[0].x, mx = v[0].x;
#pragma unroll
        for (int i = 0; i < VEC_PER_T; ++i) {
            mn = fminf(mn, v[i].x); mx = fmaxf(mx, v[i].x);
            mn = fminf(mn, v[i].y); mx = fmaxf(mx, v[i].y);
            mn = fminf(mn, v[i].z); mx = fmaxf(mx, v[i].z);
            mn = fminf(mn, v[i].w); mx = fmaxf(mx, v[i].w);
        }

        // ---- warp reduce ----
#pragma unroll
        for (int off = 16; off > 0; off >>= 1) {
            mn = fminf(mn, __shfl_xor_sync(0xFFFFFFFFu, mn, off));
            mx = fmaxf(mx, __shfl_xor_sync(0xFFFFFFFFu, mx, off));
        }

        // ---- cross-warp reduce (parity slot; no trailing barrier needed) ----
        if (lid == 0) { smn[parity][wid] = mn; smx[parity][wid] = mx; }
        __syncthreads();
        if (wid == 0) {
            float a = (lid < NWARPS) ? smn[parity][lid] :  3.4e38f;
            float b = (lid < NWARPS) ? smx[parity][lid] : -3.4e38f;
#pragma unroll
            for (int off = 4; off > 0; off >>= 1) {
                a = fminf(a, __shfl_xor_sync(0xFFFFFFFFu, a, off));
                b = fmaxf(b, __shfl_xor_sync(0xFFFFFFFFu, b, off));
            }
            if (lid == 0) { smn[parity][0] = a; smx[parity][0] = b; }
        }
        __syncthreads();
        const float xmin = smn[parity][0];
        const float xmax = smx[parity][0];

        // ---- scale / zero_point (IEEE-RN; one divide per row) ----
        float scale = __fdiv_rn(xmax - xmin, QMAX_F);
        scale = fminf(fmaxf(scale, CLIPMIN_F), CLIPMAX_F);
        float zp = __fdiv_rn(-xmin, scale);
        zp = fminf(fmaxf(zp, -CLIPMAX_F), CLIPMAX_F);
        const float inv_scale = __fdiv_rn(1.0f, scale);

        // ---- quantize from registers, store (streaming) ----
        float* __restrict__ obase = out + (long long)row * ROW_LEN;
        float4* __restrict__ orow = reinterpret_cast<float4*>(obase);
#pragma unroll
        for (int i = 0; i < VEC_PER_T; ++i) {
            float4 o;
            {
                float xi = rintf(v[i].x * inv_scale) + zp;
                xi = fminf(fmaxf(xi, 0.0f), QMAX_F);
                o.x = (xi - zp) * scale;
            }
            {
                float xi = rintf(v[i].y * inv_scale) + zp;
                xi = fminf(fmaxf(xi, 0.0f), QMAX_F);
                o.y = (xi - zp) * scale;
            }
            {
                float xi = rintf(v[i].z * inv_scale) + zp;
                xi = fminf(fmaxf(xi, 0.0f), QMAX_F);
                o.z = (xi - zp) * scale;
            }
            {
                float xi = rintf(v[i].w * inv_scale) + zp;
                xi = fminf(fmaxf(xi, 0.0f), QMAX_F);
                o.w = (xi - zp) * scale;
            }
            __stcs(&orow[tid + i * NTHREADS], o);
        }

        // ---- rotate prefetch buffer ----
#pragma unroll
        for (int i = 0; i < VEC_PER_T; ++i) v[i] = vn[i];
    }
}

extern "C" void kernel_launch(void* const* d_in, const int* in_sizes, int n_in,
                              void* d_out, int out_size)
{
    const float* x = (const float*)d_in[0];
    float* out = (float*)d_out;
    const int n_rows = in_sizes[0] / ROW_LEN;   // 16384

    int dev = 0;
    cudaGetDevice(&dev);
    int sms = 148;
    cudaDeviceGetAttribute(&sms, cudaDevAttrMultiProcessorCount, dev);
    int occ = 4;
    cudaOccupancyMaxActiveBlocksPerMultiprocessor(&occ, act_quant_kernel,
                                                  NTHREADS, 0);
    if (occ < 1) occ = 1;
    int grid = sms * occ;
    if (grid > n_rows) grid = n_rows;

    act_quant_kernel<<<grid, NTHREADS>>>(x, out, n_rows);
}